// round 1
// baseline (speedup 1.0000x reference)
#include <cuda_runtime.h>
#include <math.h>

#define B_ 8
#define T_ 2048
#define C_ 1024
#define H_ 64

// Scratch for projected q/k/v (post-RoPE). Static __device__ arrays: allowed.
__device__ float g_Q[B_*T_*H_];
__device__ float g_K[B_*T_*H_];
__device__ float g_V[B_*T_*H_];

// ---------------------------------------------------------------------------
// Kernel 1: q/k/v = x @ W{q,k,v}, RoPE applied to q,k in the epilogue.
// Grid: (B*T/64) blocks of 256 threads. Each block: 64 rows x 64 cols x 3 mats.
// 4x4 register microtiles, smem-staged x (64x32) and W (32x64) chunks.
// ---------------------------------------------------------------------------
__global__ __launch_bounds__(256) void proj_rope_kernel(
    const float* __restrict__ x,  const float* __restrict__ Wq,
    const float* __restrict__ Wk, const float* __restrict__ Wv)
{
    __shared__ float xs[64][33];
    __shared__ float wq[32][65];
    __shared__ float wk[32][65];
    __shared__ float wv[32][65];

    const int tid  = threadIdx.x;
    const int tr   = tid >> 4;   // 0..15 -> rows tr*4..tr*4+3
    const int tc   = tid & 15;   // 0..15 -> cols tc*4..tc*4+3
    const int row0 = blockIdx.x * 64;

    float aq[4][4], ak[4][4], av[4][4];
    #pragma unroll
    for (int i = 0; i < 4; i++)
        #pragma unroll
        for (int j = 0; j < 4; j++) { aq[i][j] = 0.f; ak[i][j] = 0.f; av[i][j] = 0.f; }

    for (int kc = 0; kc < C_; kc += 32) {
        __syncthreads();
        #pragma unroll
        for (int i = tid; i < 64*32; i += 256) {
            int r = i >> 5, k = i & 31;
            xs[r][k] = x[(size_t)(row0 + r) * C_ + kc + k];
        }
        #pragma unroll
        for (int i = tid; i < 32*64; i += 256) {
            int k = i >> 6, c = i & 63;
            wq[k][c] = Wq[(size_t)(kc + k) * H_ + c];
            wk[k][c] = Wk[(size_t)(kc + k) * H_ + c];
            wv[k][c] = Wv[(size_t)(kc + k) * H_ + c];
        }
        __syncthreads();

        #pragma unroll 8
        for (int k = 0; k < 32; k++) {
            float xr[4];
            #pragma unroll
            for (int i = 0; i < 4; i++) xr[i] = xs[tr*4 + i][k];
            float q4[4], k4[4], v4[4];
            #pragma unroll
            for (int j = 0; j < 4; j++) {
                q4[j] = wq[k][tc*4 + j];
                k4[j] = wk[k][tc*4 + j];
                v4[j] = wv[k][tc*4 + j];
            }
            #pragma unroll
            for (int i = 0; i < 4; i++)
                #pragma unroll
                for (int j = 0; j < 4; j++) {
                    aq[i][j] = fmaf(xr[i], q4[j], aq[i][j]);
                    ak[i][j] = fmaf(xr[i], k4[j], ak[i][j]);
                    av[i][j] = fmaf(xr[i], v4[j], av[i][j]);
                }
        }
    }

    // RoPE epilogue: interleaved pairs (2p, 2p+1), pair index pi = col/2.
    // out[2p]   = x0*cos - x1*sin ; out[2p+1] = x1*cos + x0*sin
    #pragma unroll
    for (int i = 0; i < 4; i++) {
        int grow = row0 + tr*4 + i;
        int t    = grow & (T_ - 1);     // T_ is a power of two
        #pragma unroll
        for (int p = 0; p < 2; p++) {
            int c0 = tc*4 + 2*p;
            int pi = c0 >> 1;
            float inv = powf(10000.f, -(float)pi * (1.f / 32.f));
            float ang = (float)t * inv;
            float sn, cs;
            sincosf(ang, &sn, &cs);
            float q0 = aq[i][2*p], q1 = aq[i][2*p+1];
            float k0 = ak[i][2*p], k1 = ak[i][2*p+1];
            size_t base = (size_t)grow * H_ + c0;
            g_Q[base]     = q0*cs - q1*sn;
            g_Q[base + 1] = q1*cs + q0*sn;
            g_K[base]     = k0*cs - k1*sn;
            g_K[base + 1] = k1*cs + k0*sn;
            g_V[base]     = av[i][2*p];
            g_V[base + 1] = av[i][2*p+1];
        }
    }
}

// ---------------------------------------------------------------------------
// Kernel 2: causal flash attention, fp32.
// Grid: (T/64, B). 256 threads. 64-query tile per CTA, loops over <=qt+1 KV
// tiles of 64. 4x4 register microtiles for S=QK^T and O+=PV; online softmax
// with 16-lane shfl reductions (threads sharing a row group live in one
// 16-lane half-warp). smem stride 65 avoids bank conflicts.
// ---------------------------------------------------------------------------
__global__ __launch_bounds__(256) void attn_kernel(float* __restrict__ out)
{
    extern __shared__ float sm[];
    float* sQ = sm;                 // 64*65
    float* sK = sQ + 64*65;
    float* sV = sK + 64*65;
    float* sP = sV + 64*65;

    const int tid = threadIdx.x;
    const int tr  = tid >> 4;       // row group
    const int tc  = tid & 15;       // col group
    const int b   = blockIdx.y;
    const int qt  = blockIdx.x;

    const float* Qb = g_Q + ((size_t)b * T_ + qt * 64) * H_;
    for (int i = tid; i < 64*64; i += 256) {
        int r = i >> 6, c = i & 63;
        sQ[r*65 + c] = Qb[i];
    }

    float m_i[4], l_i[4], acc[4][4];
    #pragma unroll
    for (int i = 0; i < 4; i++) {
        m_i[i] = -1e30f; l_i[i] = 0.f;
        #pragma unroll
        for (int j = 0; j < 4; j++) acc[i][j] = 0.f;
    }

    const int nkt = qt + 1;
    for (int kt = 0; kt < nkt; kt++) {
        __syncthreads();   // protect sK/sV/sP from previous iteration readers
        const float* Kb = g_K + ((size_t)b * T_ + kt * 64) * H_;
        const float* Vb = g_V + ((size_t)b * T_ + kt * 64) * H_;
        for (int i = tid; i < 64*64; i += 256) {
            int r = i >> 6, c = i & 63;
            sK[r*65 + c] = Kb[i];
            sV[r*65 + c] = Vb[i];
        }
        __syncthreads();

        // S = Q K^T (4x4 microtile)
        float s[4][4];
        #pragma unroll
        for (int i = 0; i < 4; i++)
            #pragma unroll
            for (int j = 0; j < 4; j++) s[i][j] = 0.f;

        #pragma unroll 8
        for (int h = 0; h < 64; h++) {
            float qv[4], kv[4];
            #pragma unroll
            for (int i = 0; i < 4; i++) qv[i] = sQ[(tr*4 + i)*65 + h];
            #pragma unroll
            for (int j = 0; j < 4; j++) kv[j] = sK[(tc*4 + j)*65 + h];
            #pragma unroll
            for (int i = 0; i < 4; i++)
                #pragma unroll
                for (int j = 0; j < 4; j++)
                    s[i][j] = fmaf(qv[i], kv[j], s[i][j]);
        }

        const float scale = 0.125f;   // 1/sqrt(64)
        if (kt == qt) {
            #pragma unroll
            for (int i = 0; i < 4; i++)
                #pragma unroll
                for (int j = 0; j < 4; j++) {
                    int r = tr*4 + i, c = tc*4 + j;
                    s[i][j] = (c <= r) ? s[i][j] * scale : -1e30f;
                }
        } else {
            #pragma unroll
            for (int i = 0; i < 4; i++)
                #pragma unroll
                for (int j = 0; j < 4; j++) s[i][j] *= scale;
        }

        // Online softmax per row (replicated across the 16 col-group threads)
        float p[4][4];
        #pragma unroll
        for (int i = 0; i < 4; i++) {
            float mx = fmaxf(fmaxf(s[i][0], s[i][1]), fmaxf(s[i][2], s[i][3]));
            mx = fmaxf(mx, __shfl_xor_sync(0xffffffffu, mx, 1));
            mx = fmaxf(mx, __shfl_xor_sync(0xffffffffu, mx, 2));
            mx = fmaxf(mx, __shfl_xor_sync(0xffffffffu, mx, 4));
            mx = fmaxf(mx, __shfl_xor_sync(0xffffffffu, mx, 8));
            float mnew  = fmaxf(m_i[i], mx);
            float alpha = __expf(m_i[i] - mnew);
            float rs = 0.f;
            #pragma unroll
            for (int j = 0; j < 4; j++) {
                p[i][j] = __expf(s[i][j] - mnew);
                rs += p[i][j];
            }
            rs += __shfl_xor_sync(0xffffffffu, rs, 1);
            rs += __shfl_xor_sync(0xffffffffu, rs, 2);
            rs += __shfl_xor_sync(0xffffffffu, rs, 4);
            rs += __shfl_xor_sync(0xffffffffu, rs, 8);
            l_i[i] = l_i[i] * alpha + rs;
            m_i[i] = mnew;
            #pragma unroll
            for (int j = 0; j < 4; j++) acc[i][j] *= alpha;
        }

        // Stage P into smem for the PV GEMM
        #pragma unroll
        for (int i = 0; i < 4; i++)
            #pragma unroll
            for (int j = 0; j < 4; j++)
                sP[(tr*4 + i)*65 + tc*4 + j] = p[i][j];
        __syncthreads();

        // O += P @ V (4x4 microtile over n)
        #pragma unroll 8
        for (int n = 0; n < 64; n++) {
            float pv[4], vv[4];
            #pragma unroll
            for (int i = 0; i < 4; i++) pv[i] = sP[(tr*4 + i)*65 + n];
            #pragma unroll
            for (int j = 0; j < 4; j++) vv[j] = sV[n*65 + tc*4 + j];
            #pragma unroll
            for (int i = 0; i < 4; i++)
                #pragma unroll
                for (int j = 0; j < 4; j++)
                    acc[i][j] = fmaf(pv[i], vv[j], acc[i][j]);
        }
    }

    float* ob = out + ((size_t)b * T_ + qt * 64) * H_;
    #pragma unroll
    for (int i = 0; i < 4; i++) {
        float rcp = 1.f / l_i[i];
        #pragma unroll
        for (int j = 0; j < 4; j++)
            ob[(tr*4 + i)*H_ + tc*4 + j] = acc[i][j] * rcp;
    }
}

extern "C" void kernel_launch(void* const* d_in, const int* in_sizes, int n_in,
                              void* d_out, int out_size)
{
    const float* x  = (const float*)d_in[0];
    const float* Wq = (const float*)d_in[1];
    const float* Wk = (const float*)d_in[2];
    const float* Wv = (const float*)d_in[3];
    float* out = (float*)d_out;

    const int smem_bytes = 4 * 64 * 65 * (int)sizeof(float);  // 66560
    cudaFuncSetAttribute(attn_kernel,
                         cudaFuncAttributeMaxDynamicSharedMemorySize, smem_bytes);

    proj_rope_kernel<<<(B_ * T_) / 64, 256>>>(x, Wq, Wk, Wv);
    attn_kernel<<<dim3(T_ / 64, B_), 256, smem_bytes>>>(out);
}

// round 2
// speedup vs baseline: 1.2078x; 1.2078x over previous
#include <cuda_runtime.h>
#include <math.h>

#define B_ 8
#define T_ 2048
#define C_ 1024
#define H_ 64

typedef unsigned long long ull;

__device__ float g_Q[B_*T_*H_];
__device__ float g_K[B_*T_*H_];
__device__ float g_V[B_*T_*H_];

// ---- packed f32x2 helpers (sm_103a) ---------------------------------------
__device__ __forceinline__ ull pack2(float x) {
    ull r; asm("mov.b64 %0, {%1, %1};" : "=l"(r) : "f"(x)); return r;
}
__device__ __forceinline__ void unpack2(ull v, float& lo, float& hi) {
    asm("mov.b64 {%0, %1}, %2;" : "=f"(lo), "=f"(hi) : "l"(v));
}
__device__ __forceinline__ void ffma2(ull& d, ull a, ull b) {
    asm("fma.rn.f32x2 %0, %1, %2, %0;" : "+l"(d) : "l"(a), "l"(b));
}
__device__ __forceinline__ ull fmul2(ull a, ull b) {
    ull r; asm("mul.rn.f32x2 %0, %1, %2;" : "=l"(r) : "l"(a), "l"(b)); return r;
}

// ---------------------------------------------------------------------------
// Kernel 1: q/k/v = x @ W{q,k,v} with RoPE fused. 64 rows x 64 cols x 3 mats
// per CTA, f32x2-packed along output columns. x staged DUPLICATED in smem so
// the broadcast pack is done once at load time.
// ---------------------------------------------------------------------------
__global__ __launch_bounds__(256) void proj_rope_kernel(
    const float* __restrict__ x,  const float* __restrict__ Wq,
    const float* __restrict__ Wk, const float* __restrict__ Wv)
{
    __shared__ __align__(16) float xsd[64][66];   // duplicated: [r][2k],[r][2k+1] = x
    __shared__ __align__(16) float wq[32][66];
    __shared__ __align__(16) float wk[32][66];
    __shared__ __align__(16) float wv[32][66];

    const int tid  = threadIdx.x;
    const int tr   = tid >> 4;    // 0..15 -> rows tr*4..+3
    const int tc   = tid & 15;    // 0..15 -> cols tc*4..+3 (2 packed pairs)
    const int row0 = blockIdx.x * 64;

    ull aq2[4][2], ak2[4][2], av2[4][2];
    #pragma unroll
    for (int i = 0; i < 4; i++)
        #pragma unroll
        for (int p = 0; p < 2; p++) { aq2[i][p] = 0ull; ak2[i][p] = 0ull; av2[i][p] = 0ull; }

    for (int kc = 0; kc < C_; kc += 32) {
        __syncthreads();
        #pragma unroll
        for (int i = tid; i < 64*32; i += 256) {
            int r = i >> 5, k = i & 31;
            float v = x[(size_t)(row0 + r) * C_ + kc + k];
            *reinterpret_cast<ull*>(&xsd[r][2*k]) = pack2(v);
        }
        #pragma unroll
        for (int i = tid; i < 32*64; i += 256) {
            int k = i >> 6, c = i & 63;
            wq[k][c] = Wq[(size_t)(kc + k) * H_ + c];
            wk[k][c] = Wk[(size_t)(kc + k) * H_ + c];
            wv[k][c] = Wv[(size_t)(kc + k) * H_ + c];
        }
        __syncthreads();

        #pragma unroll 4
        for (int k = 0; k < 32; k++) {
            ull xp[4];
            #pragma unroll
            for (int i = 0; i < 4; i++)
                xp[i] = *reinterpret_cast<const ull*>(&xsd[tr*4 + i][2*k]);
            const ull* wqr = reinterpret_cast<const ull*>(&wq[k][0]);
            const ull* wkr = reinterpret_cast<const ull*>(&wk[k][0]);
            const ull* wvr = reinterpret_cast<const ull*>(&wv[k][0]);
            ull q2[2] = { wqr[tc*2], wqr[tc*2+1] };
            ull k2[2] = { wkr[tc*2], wkr[tc*2+1] };
            ull v2[2] = { wvr[tc*2], wvr[tc*2+1] };
            #pragma unroll
            for (int i = 0; i < 4; i++)
                #pragma unroll
                for (int p = 0; p < 2; p++) {
                    ffma2(aq2[i][p], xp[i], q2[p]);
                    ffma2(ak2[i][p], xp[i], k2[p]);
                    ffma2(av2[i][p], xp[i], v2[p]);
                }
        }
    }

    // RoPE epilogue: packed pair p holds interleaved cols (tc*4+2p, tc*4+2p+1)
    float inv[2];
    #pragma unroll
    for (int p = 0; p < 2; p++) {
        int pi = tc*2 + p;                        // (tc*4+2p)/2
        inv[p] = powf(10000.f, -(float)pi * (1.f / 32.f));
    }
    #pragma unroll
    for (int i = 0; i < 4; i++) {
        int grow = row0 + tr*4 + i;
        int t    = grow & (T_ - 1);
        #pragma unroll
        for (int p = 0; p < 2; p++) {
            float sn, cs;
            sincosf((float)t * inv[p], &sn, &cs);
            float q0, q1, k0, k1, v0, v1;
            unpack2(aq2[i][p], q0, q1);
            unpack2(ak2[i][p], k0, k1);
            unpack2(av2[i][p], v0, v1);
            size_t base = (size_t)grow * H_ + tc*4 + 2*p;
            g_Q[base]     = q0*cs - q1*sn;
            g_Q[base + 1] = q1*cs + q0*sn;
            g_K[base]     = k0*cs - k1*sn;
            g_K[base + 1] = k1*cs + k0*sn;
            g_V[base]     = v0;
            g_V[base + 1] = v1;
        }
    }
}

// ---------------------------------------------------------------------------
// Kernel 2: causal flash attention, f32x2-packed, load-balanced.
// Each CTA processes the PAIR of query tiles (bx, 31-bx): exactly 33 KV-tile
// iterations per CTA -> 128 uniform CTAs, one balanced wave.
// QK^T packs along the h-reduction (contiguous LDS.64 on both operands).
// PV packs along output columns; P staged duplicated for broadcast packs.
// Thread->data maps chosen for conflict-free LDS.64.
// ---------------------------------------------------------------------------
__global__ __launch_bounds__(256) void attn_kernel(float* __restrict__ out)
{
    extern __shared__ __align__(16) float sm[];
    float* sQ  = sm;                 // 64*66
    float* sK  = sQ + 64*66;
    float* sV  = sK + 64*66;
    float* sPd = sV + 64*66;         // 64*132 duplicated P

    const int tid = threadIdx.x;
    const int tr  = tid >> 4;        // query-row group 0..15
    const int tc  = tid & 15;
    const int b   = blockIdx.y;
    const float scale = 0.125f;      // 1/sqrt(64)

    #pragma unroll 1
    for (int pass = 0; pass < 2; pass++) {
        const int qt = pass ? (31 - (int)blockIdx.x) : (int)blockIdx.x;

        __syncthreads();
        const float* Qb = g_Q + ((size_t)b * T_ + qt * 64) * H_;
        for (int i = tid; i < 64*64; i += 256) {
            int r = i >> 6, c = i & 63;
            sQ[r*66 + c] = Qb[i];
        }

        float m_i[4], l_i[4];
        ull acc2[4][2];
        #pragma unroll
        for (int i = 0; i < 4; i++) {
            m_i[i] = -1e30f; l_i[i] = 0.f;
            acc2[i][0] = 0ull; acc2[i][1] = 0ull;
        }

        for (int kt = 0; kt <= qt; kt++) {
            __syncthreads();
            const float* Kb = g_K + ((size_t)b * T_ + kt * 64) * H_;
            const float* Vb = g_V + ((size_t)b * T_ + kt * 64) * H_;
            for (int i = tid; i < 64*64; i += 256) {
                int r = i >> 6, c = i & 63;
                sK[r*66 + c] = Kb[i];
                sV[r*66 + c] = Vb[i];
            }
            __syncthreads();

            // ---- S = Q K^T, packed along h. k-col for (tc,j) = tc + j*16 ----
            ull s2[4][4];
            #pragma unroll
            for (int i = 0; i < 4; i++)
                #pragma unroll
                for (int j = 0; j < 4; j++) s2[i][j] = 0ull;

            #pragma unroll 4
            for (int h = 0; h < 64; h += 2) {
                ull q2[4], k2[4];
                #pragma unroll
                for (int i = 0; i < 4; i++)
                    q2[i] = *reinterpret_cast<const ull*>(&sQ[(tr*4 + i)*66 + h]);
                #pragma unroll
                for (int j = 0; j < 4; j++)
                    k2[j] = *reinterpret_cast<const ull*>(&sK[(tc + j*16)*66 + h]);
                #pragma unroll
                for (int i = 0; i < 4; i++)
                    #pragma unroll
                    for (int j = 0; j < 4; j++)
                        ffma2(s2[i][j], q2[i], k2[j]);
            }

            float s[4][4];
            #pragma unroll
            for (int i = 0; i < 4; i++)
                #pragma unroll
                for (int j = 0; j < 4; j++) {
                    float lo, hi; unpack2(s2[i][j], lo, hi);
                    s[i][j] = (lo + hi) * scale;
                }

            if (kt == qt) {
                #pragma unroll
                for (int i = 0; i < 4; i++)
                    #pragma unroll
                    for (int j = 0; j < 4; j++) {
                        int r = tr*4 + i, c = tc + j*16;
                        if (c > r) s[i][j] = -1e30f;
                    }
            }

            // ---- online softmax (rows replicated across 16 tc lanes) ----
            #pragma unroll
            for (int i = 0; i < 4; i++) {
                float mx = fmaxf(fmaxf(s[i][0], s[i][1]), fmaxf(s[i][2], s[i][3]));
                mx = fmaxf(mx, __shfl_xor_sync(0xffffffffu, mx, 1));
                mx = fmaxf(mx, __shfl_xor_sync(0xffffffffu, mx, 2));
                mx = fmaxf(mx, __shfl_xor_sync(0xffffffffu, mx, 4));
                mx = fmaxf(mx, __shfl_xor_sync(0xffffffffu, mx, 8));
                float mnew  = fmaxf(m_i[i], mx);
                float alpha = __expf(m_i[i] - mnew);
                float rs = 0.f;
                float p[4];
                #pragma unroll
                for (int j = 0; j < 4; j++) { p[j] = __expf(s[i][j] - mnew); rs += p[j]; }
                rs += __shfl_xor_sync(0xffffffffu, rs, 1);
                rs += __shfl_xor_sync(0xffffffffu, rs, 2);
                rs += __shfl_xor_sync(0xffffffffu, rs, 4);
                rs += __shfl_xor_sync(0xffffffffu, rs, 8);
                l_i[i] = l_i[i] * alpha + rs;
                m_i[i] = mnew;
                ull a2 = pack2(alpha);
                acc2[i][0] = fmul2(acc2[i][0], a2);
                acc2[i][1] = fmul2(acc2[i][1], a2);
                // stage P duplicated: sPd[row][2n],[2n+1] = p  (n = tc + j*16)
                #pragma unroll
                for (int j = 0; j < 4; j++)
                    *reinterpret_cast<ull*>(&sPd[(tr*4 + i)*132 + 2*(tc + j*16)]) = pack2(p[j]);
            }
            __syncthreads();

            // ---- O += P @ V, packed along output cols (tc*2 + jp*32) ----
            #pragma unroll 4
            for (int n = 0; n < 64; n++) {
                ull pv2[4], vv2[2];
                #pragma unroll
                for (int i = 0; i < 4; i++)
                    pv2[i] = *reinterpret_cast<const ull*>(&sPd[(tr*4 + i)*132 + 2*n]);
                vv2[0] = *reinterpret_cast<const ull*>(&sV[n*66 + tc*2]);
                vv2[1] = *reinterpret_cast<const ull*>(&sV[n*66 + tc*2 + 32]);
                #pragma unroll
                for (int i = 0; i < 4; i++) {
                    ffma2(acc2[i][0], pv2[i], vv2[0]);
                    ffma2(acc2[i][1], pv2[i], vv2[1]);
                }
            }
        }

        float* ob = out + ((size_t)b * T_ + qt * 64) * H_;
        #pragma unroll
        for (int i = 0; i < 4; i++) {
            float rcp = 1.f / l_i[i];
            #pragma unroll
            for (int jp = 0; jp < 2; jp++) {
                float lo, hi; unpack2(acc2[i][jp], lo, hi);
                float2 v = make_float2(lo * rcp, hi * rcp);
                *reinterpret_cast<float2*>(&ob[(tr*4 + i)*H_ + tc*2 + jp*32]) = v;
            }
        }
    }
}

extern "C" void kernel_launch(void* const* d_in, const int* in_sizes, int n_in,
                              void* d_out, int out_size)
{
    const float* x  = (const float*)d_in[0];
    const float* Wq = (const float*)d_in[1];
    const float* Wk = (const float*)d_in[2];
    const float* Wv = (const float*)d_in[3];
    float* out = (float*)d_out;

    const int smem_bytes = (3 * 64 * 66 + 64 * 132) * (int)sizeof(float); // 84480
    cudaFuncSetAttribute(attn_kernel,
                         cudaFuncAttributeMaxDynamicSharedMemorySize, smem_bytes);

    proj_rope_kernel<<<(B_ * T_) / 64, 256>>>(x, Wq, Wk, Wv);
    attn_kernel<<<dim3(16, B_), 256, smem_bytes>>>(out);
}

// round 4
// speedup vs baseline: 1.9706x; 1.6316x over previous
#include <cuda_runtime.h>
#include <cuda_bf16.h>
#include <math.h>
#include <stdint.h>

#define B_ 8
#define T_ 2048
#define C_ 1024
#define H_ 64

typedef unsigned long long ull;

__device__ float g_Q[B_*T_*H_];
__device__ float g_K[B_*T_*H_];
__device__ float g_V[B_*T_*H_];
// W split into bf16 hi/lo, K-major: [n (0..191)][k (0..1023)]; n: q 0-63, k 64-127, v 128-191
__device__ __align__(16) __nv_bfloat16 g_Bhi[192*1024];
__device__ __align__(16) __nv_bfloat16 g_Blo[192*1024];

// ---- packed f32x2 helpers (sm_103) ----------------------------------------
__device__ __forceinline__ ull pack2(float x) {
    ull r; asm("mov.b64 %0, {%1, %1};" : "=l"(r) : "f"(x)); return r;
}
__device__ __forceinline__ void unpack2(ull v, float& lo, float& hi) {
    asm("mov.b64 {%0, %1}, %2;" : "=f"(lo), "=f"(hi) : "l"(v));
}
__device__ __forceinline__ void ffma2(ull& d, ull a, ull b) {
    asm("fma.rn.f32x2 %0, %1, %2, %0;" : "+l"(d) : "l"(a), "l"(b));
}
__device__ __forceinline__ ull fmul2(ull a, ull b) {
    ull r; asm("mul.rn.f32x2 %0, %1, %2;" : "=l"(r) : "l"(a), "l"(b)); return r;
}

__device__ __forceinline__ uint32_t smem_u32(const void* p) {
    uint32_t a;
    asm("{ .reg .u64 t; cvta.to.shared.u64 t, %1; cvt.u32.u64 %0, t; }" : "=r"(a) : "l"(p));
    return a;
}
__device__ __forceinline__ void ldmx4(uint32_t& r0, uint32_t& r1, uint32_t& r2, uint32_t& r3,
                                      uint32_t addr) {
    asm volatile("ldmatrix.sync.aligned.m8n8.x4.shared.b16 {%0,%1,%2,%3}, [%4];"
                 : "=r"(r0), "=r"(r1), "=r"(r2), "=r"(r3) : "r"(addr));
}
__device__ __forceinline__ void mma16816(float& c0, float& c1, float& c2, float& c3,
                                         uint32_t a0, uint32_t a1, uint32_t a2, uint32_t a3,
                                         uint32_t b0, uint32_t b1) {
    asm volatile("mma.sync.aligned.m16n8k16.row.col.f32.bf16.bf16.f32 "
                 "{%0,%1,%2,%3}, {%4,%5,%6,%7}, {%8,%9}, {%0,%1,%2,%3};"
                 : "+f"(c0), "+f"(c1), "+f"(c2), "+f"(c3)
                 : "r"(a0), "r"(a1), "r"(a2), "r"(a3), "r"(b0), "r"(b1));
}
__device__ __forceinline__ uint32_t bf16x2(float a, float b) {
    __nv_bfloat16 h0 = __float2bfloat16(a), h1 = __float2bfloat16(b);
    return (uint32_t)__bfloat16_as_ushort(h0) | ((uint32_t)__bfloat16_as_ushort(h1) << 16);
}

// ---------------------------------------------------------------------------
// Prep: split W{q,k,v} (fp32 [K=1024][64]) into bf16 hi/lo, K-major [192][1024]
// ---------------------------------------------------------------------------
__global__ __launch_bounds__(256) void prep_B_kernel(
    const float* __restrict__ Wq, const float* __restrict__ Wk, const float* __restrict__ Wv)
{
    int idx = blockIdx.x * 256 + threadIdx.x;      // 0 .. 192*1024-1
    int n = idx >> 10, k = idx & 1023;
    const float* W = (n < 64) ? Wq : (n < 128) ? Wk : Wv;
    float v = W[k * 64 + (n & 63)];
    __nv_bfloat16 h = __float2bfloat16(v);
    g_Bhi[idx] = h;
    g_Blo[idx] = __float2bfloat16(v - __bfloat162float(h));
}

// ---------------------------------------------------------------------------
// Projection GEMM on mma.sync (HMMA bf16, hi/lo split = fp32-accurate).
// Per CTA: M=128 rows, N=192 (Q|K|V). 512 threads = 16 warps in 4x4 grid,
// warp tile 32x48. K in 16 chunks of 64. RoPE fused in epilogue.
// smem: Ahi/Alo [128][72] b16, Bhi/Blo [192][72] b16 (stride 144B).
// ---------------------------------------------------------------------------
#define PA_STR 72
#define SM_AHI 0
#define SM_ALO (128*PA_STR*2)             // 18432
#define SM_BHI (2*128*PA_STR*2)           // 36864
#define SM_BLO (SM_BHI + 192*PA_STR*2)    // 64512
#define SM_TOT (SM_BLO + 192*PA_STR*2)    // 92160

__global__ __launch_bounds__(512) void proj_gemm_kernel(const float* __restrict__ x)
{
    extern __shared__ char smem[];
    const uint32_t sbase = smem_u32(smem);
    const int tid    = threadIdx.x;
    const int wid    = tid >> 5;
    const int lane   = tid & 31;
    const int warp_m = wid >> 2;          // 0..3 -> rows warp_m*32
    const int warp_n = wid & 3;           // 0..3 -> cols warp_n*48
    const int m0     = blockIdx.x * 128;

    // ldmatrix per-lane byte offsets (tile-relative)
    uint32_t aOff[2], bOff[3];
    {
        int mlo = (lane >> 3) & 1, khi = (lane >> 4) & 1, r8 = lane & 7;
        #pragma unroll
        for (int mt = 0; mt < 2; mt++)
            aOff[mt] = (uint32_t)((warp_m*32 + mt*16 + mlo*8 + r8) * (PA_STR*2) + khi*16);
        #pragma unroll
        for (int p = 0; p < 3; p++)
            bOff[p] = (uint32_t)((warp_n*48 + p*16 + khi*8 + r8) * (PA_STR*2) + mlo*16);
    }

    float acc[2][6][4];
    #pragma unroll
    for (int mt = 0; mt < 2; mt++)
        #pragma unroll
        for (int nt = 0; nt < 6; nt++)
            #pragma unroll
            for (int q = 0; q < 4; q++) acc[mt][nt][q] = 0.f;

    #pragma unroll 1
    for (int c = 0; c < 16; c++) {
        const int kc = c * 64;
        if (c > 0) __syncthreads();

        // ---- A: x fp32 -> bf16 hi/lo into smem ----
        #pragma unroll
        for (int it = tid; it < 2048; it += 512) {
            int r = it >> 4, q = it & 15;
            float4 f = *reinterpret_cast<const float4*>(x + (size_t)(m0 + r) * C_ + kc + q*4);
            uint32_t h0 = bf16x2(f.x, f.y), h1 = bf16x2(f.z, f.w);
            float rx = f.x - __bfloat162float(__ushort_as_bfloat16((unsigned short)(h0 & 0xffff)));
            float ry = f.y - __bfloat162float(__ushort_as_bfloat16((unsigned short)(h0 >> 16)));
            float rz = f.z - __bfloat162float(__ushort_as_bfloat16((unsigned short)(h1 & 0xffff)));
            float rw = f.w - __bfloat162float(__ushort_as_bfloat16((unsigned short)(h1 >> 16)));
            uint32_t l0 = bf16x2(rx, ry), l1 = bf16x2(rz, rw);
            uint32_t off = (uint32_t)(r * (PA_STR*2) + q * 8);
            *reinterpret_cast<uint2*>(smem + SM_AHI + off) = make_uint2(h0, h1);
            *reinterpret_cast<uint2*>(smem + SM_ALO + off) = make_uint2(l0, l1);
        }
        // ---- B: copy pre-split bf16 ----
        #pragma unroll
        for (int it = tid; it < 1536; it += 512) {
            int n = it >> 3, s = it & 7;
            uint32_t off = (uint32_t)(n * (PA_STR*2) + s * 16);
            *reinterpret_cast<uint4*>(smem + SM_BHI + off) =
                *reinterpret_cast<const uint4*>(g_Bhi + (size_t)n * 1024 + kc + s*8);
            *reinterpret_cast<uint4*>(smem + SM_BLO + off) =
                *reinterpret_cast<const uint4*>(g_Blo + (size_t)n * 1024 + kc + s*8);
        }
        __syncthreads();

        // ---- 3 split passes: hi*hi, hi*lo, lo*hi ----
        #pragma unroll 1
        for (int pass = 0; pass < 3; pass++) {
            uint32_t aBase = sbase + ((pass < 2) ? SM_AHI : SM_ALO);
            uint32_t bBase = sbase + ((pass == 1) ? SM_BLO : SM_BHI);
            #pragma unroll
            for (int ks = 0; ks < 4; ks++) {
                uint32_t kb = (uint32_t)(ks * 32);     // 16 b16 = 32 bytes
                uint32_t a[2][4];
                #pragma unroll
                for (int mt = 0; mt < 2; mt++)
                    ldmx4(a[mt][0], a[mt][1], a[mt][2], a[mt][3], aBase + aOff[mt] + kb);
                uint32_t b[6][2];
                #pragma unroll
                for (int p = 0; p < 3; p++) {
                    uint32_t r0, r1, r2, r3;
                    ldmx4(r0, r1, r2, r3, bBase + bOff[p] + kb);
                    b[p*2][0] = r0; b[p*2][1] = r1;
                    b[p*2+1][0] = r2; b[p*2+1][1] = r3;
                }
                #pragma unroll
                for (int mt = 0; mt < 2; mt++)
                    #pragma unroll
                    for (int nt = 0; nt < 6; nt++)
                        mma16816(acc[mt][nt][0], acc[mt][nt][1], acc[mt][nt][2], acc[mt][nt][3],
                                 a[mt][0], a[mt][1], a[mt][2], a[mt][3],
                                 b[nt][0], b[nt][1]);
            }
        }
    }

    // ---- Epilogue: RoPE + store ----
    const int g  = lane >> 2;
    const int tq = lane & 3;
    #pragma unroll
    for (int mt = 0; mt < 2; mt++) {
        int row0 = m0 + warp_m*32 + mt*16 + g;
        int rows[2] = { row0, row0 + 8 };
        #pragma unroll
        for (int nt = 0; nt < 6; nt++) {
            int n0g = warp_n*48 + nt*8;
            int col = n0g + 2*tq;
            int mat = col >> 6;
            int col_in = col & 63;
            if (mat < 2) {
                float* dst = (mat == 0) ? g_Q : g_K;
                int pi = col_in >> 1;
                float inv = powf(10000.f, -(float)pi * (1.f / 32.f));
                #pragma unroll
                for (int rg = 0; rg < 2; rg++) {
                    int t = rows[rg] & (T_ - 1);
                    float sn, cs;
                    sincosf((float)t * inv, &sn, &cs);
                    float a0 = acc[mt][nt][rg*2], a1 = acc[mt][nt][rg*2 + 1];
                    float2 v = make_float2(a0*cs - a1*sn, a1*cs + a0*sn);
                    *reinterpret_cast<float2*>(&dst[(size_t)rows[rg] * H_ + col_in]) = v;
                }
            } else {
                #pragma unroll
                for (int rg = 0; rg < 2; rg++) {
                    float2 v = make_float2(acc[mt][nt][rg*2], acc[mt][nt][rg*2 + 1]);
                    *reinterpret_cast<float2*>(&g_V[(size_t)rows[rg] * H_ + col_in]) = v;
                }
            }
        }
    }
}

// ---------------------------------------------------------------------------
// Kernel 2: causal flash attention, f32x2-packed, load-balanced (R2, proven)
// ---------------------------------------------------------------------------
__global__ __launch_bounds__(256) void attn_kernel(float* __restrict__ out)
{
    extern __shared__ __align__(16) float sm[];
    float* sQ  = sm;                 // 64*66
    float* sK  = sQ + 64*66;
    float* sV  = sK + 64*66;
    float* sPd = sV + 64*66;         // 64*132 duplicated P

    const int tid = threadIdx.x;
    const int tr  = tid >> 4;
    const int tc  = tid & 15;
    const int b   = blockIdx.y;
    const float scale = 0.125f;

    #pragma unroll 1
    for (int pass = 0; pass < 2; pass++) {
        const int qt = pass ? (31 - (int)blockIdx.x) : (int)blockIdx.x;

        __syncthreads();
        const float* Qb = g_Q + ((size_t)b * T_ + qt * 64) * H_;
        for (int i = tid; i < 64*64; i += 256) {
            int r = i >> 6, c = i & 63;
            sQ[r*66 + c] = Qb[i];
        }

        float m_i[4], l_i[4];
        ull acc2[4][2];
        #pragma unroll
        for (int i = 0; i < 4; i++) {
            m_i[i] = -1e30f; l_i[i] = 0.f;
            acc2[i][0] = 0ull; acc2[i][1] = 0ull;
        }

        for (int kt = 0; kt <= qt; kt++) {
            __syncthreads();
            const float* Kb = g_K + ((size_t)b * T_ + kt * 64) * H_;
            const float* Vb = g_V + ((size_t)b * T_ + kt * 64) * H_;
            for (int i = tid; i < 64*64; i += 256) {
                int r = i >> 6, c = i & 63;
                sK[r*66 + c] = Kb[i];
                sV[r*66 + c] = Vb[i];
            }
            __syncthreads();

            ull s2[4][4];
            #pragma unroll
            for (int i = 0; i < 4; i++)
                #pragma unroll
                for (int j = 0; j < 4; j++) s2[i][j] = 0ull;

            #pragma unroll 4
            for (int h = 0; h < 64; h += 2) {
                ull q2[4], k2[4];
                #pragma unroll
                for (int i = 0; i < 4; i++)
                    q2[i] = *reinterpret_cast<const ull*>(&sQ[(tr*4 + i)*66 + h]);
                #pragma unroll
                for (int j = 0; j < 4; j++)
                    k2[j] = *reinterpret_cast<const ull*>(&sK[(tc + j*16)*66 + h]);
                #pragma unroll
                for (int i = 0; i < 4; i++)
                    #pragma unroll
                    for (int j = 0; j < 4; j++)
                        ffma2(s2[i][j], q2[i], k2[j]);
            }

            float s[4][4];
            #pragma unroll
            for (int i = 0; i < 4; i++)
                #pragma unroll
                for (int j = 0; j < 4; j++) {
                    float lo, hi; unpack2(s2[i][j], lo, hi);
                    s[i][j] = (lo + hi) * scale;
                }

            if (kt == qt) {
                #pragma unroll
                for (int i = 0; i < 4; i++)
                    #pragma unroll
                    for (int j = 0; j < 4; j++) {
                        int r = tr*4 + i, c = tc + j*16;
                        if (c > r) s[i][j] = -1e30f;
                    }
            }

            #pragma unroll
            for (int i = 0; i < 4; i++) {
                float mx = fmaxf(fmaxf(s[i][0], s[i][1]), fmaxf(s[i][2], s[i][3]));
                mx = fmaxf(mx, __shfl_xor_sync(0xffffffffu, mx, 1));
                mx = fmaxf(mx, __shfl_xor_sync(0xffffffffu, mx, 2));
                mx = fmaxf(mx, __shfl_xor_sync(0xffffffffu, mx, 4));
                mx = fmaxf(mx, __shfl_xor_sync(0xffffffffu, mx, 8));
                float mnew  = fmaxf(m_i[i], mx);
                float alpha = __expf(m_i[i] - mnew);
                float rs = 0.f;
                float p[4];
                #pragma unroll
                for (int j = 0; j < 4; j++) { p[j] = __expf(s[i][j] - mnew); rs += p[j]; }
                rs += __shfl_xor_sync(0xffffffffu, rs, 1);
                rs += __shfl_xor_sync(0xffffffffu, rs, 2);
                rs += __shfl_xor_sync(0xffffffffu, rs, 4);
                rs += __shfl_xor_sync(0xffffffffu, rs, 8);
                l_i[i] = l_i[i] * alpha + rs;
                m_i[i] = mnew;
                ull a2 = pack2(alpha);
                acc2[i][0] = fmul2(acc2[i][0], a2);
                acc2[i][1] = fmul2(acc2[i][1], a2);
                #pragma unroll
                for (int j = 0; j < 4; j++)
                    *reinterpret_cast<ull*>(&sPd[(tr*4 + i)*132 + 2*(tc + j*16)]) = pack2(p[j]);
            }
            __syncthreads();

            #pragma unroll 4
            for (int n = 0; n < 64; n++) {
                ull pv2[4], vv2[2];
                #pragma unroll
                for (int i = 0; i < 4; i++)
                    pv2[i] = *reinterpret_cast<const ull*>(&sPd[(tr*4 + i)*132 + 2*n]);
                vv2[0] = *reinterpret_cast<const ull*>(&sV[n*66 + tc*2]);
                vv2[1] = *reinterpret_cast<const ull*>(&sV[n*66 + tc*2 + 32]);
                #pragma unroll
                for (int i = 0; i < 4; i++) {
                    ffma2(acc2[i][0], pv2[i], vv2[0]);
                    ffma2(acc2[i][1], pv2[i], vv2[1]);
                }
            }
        }

        float* ob = out + ((size_t)b * T_ + qt * 64) * H_;
        #pragma unroll
        for (int i = 0; i < 4; i++) {
            float rcp = 1.f / l_i[i];
            #pragma unroll
            for (int jp = 0; jp < 2; jp++) {
                float lo, hi; unpack2(acc2[i][jp], lo, hi);
                float2 v = make_float2(lo * rcp, hi * rcp);
                *reinterpret_cast<float2*>(&ob[(tr*4 + i)*H_ + tc*2 + jp*32]) = v;
            }
        }
    }
}

extern "C" void kernel_launch(void* const* d_in, const int* in_sizes, int n_in,
                              void* d_out, int out_size)
{
    const float* x  = (const float*)d_in[0];
    const float* Wq = (const float*)d_in[1];
    const float* Wk = (const float*)d_in[2];
    const float* Wv = (const float*)d_in[3];
    float* out = (float*)d_out;

    cudaFuncSetAttribute(proj_gemm_kernel,
                         cudaFuncAttributeMaxDynamicSharedMemorySize, SM_TOT);
    const int attn_smem = (3 * 64 * 66 + 64 * 132) * (int)sizeof(float); // 84480
    cudaFuncSetAttribute(attn_kernel,
                         cudaFuncAttributeMaxDynamicSharedMemorySize, attn_smem);

    prep_B_kernel<<<(192 * 1024) / 256, 256>>>(Wq, Wk, Wv);
    proj_gemm_kernel<<<(B_ * T_) / 128, 512, SM_TOT>>>(x);
    attn_kernel<<<dim3(16, B_), 256, attn_smem>>>(out);
}

// round 5
// speedup vs baseline: 3.5409x; 1.7968x over previous
#include <cuda_runtime.h>
#include <cuda_bf16.h>
#include <math.h>
#include <stdint.h>

#define B_ 8
#define T_ 2048
#define C_ 1024
#define H_ 64

// Q/K post-RoPE, bf16 hi/lo, row-major [B*T][64]
__device__ __align__(16) __nv_bfloat16 g_Qhi[B_*T_*H_];
__device__ __align__(16) __nv_bfloat16 g_Qlo[B_*T_*H_];
__device__ __align__(16) __nv_bfloat16 g_Khi[B_*T_*H_];
__device__ __align__(16) __nv_bfloat16 g_Klo[B_*T_*H_];
// V transposed [B][64 h][T], bf16 hi/lo
__device__ __align__(16) __nv_bfloat16 g_VThi[B_*H_*T_];
__device__ __align__(16) __nv_bfloat16 g_VTlo[B_*H_*T_];
// W split bf16 hi/lo, K-major [192][1024]
__device__ __align__(16) __nv_bfloat16 g_Bhi[192*1024];
__device__ __align__(16) __nv_bfloat16 g_Blo[192*1024];

__device__ __forceinline__ uint32_t smem_u32(const void* p) {
    uint32_t a;
    asm("{ .reg .u64 t; cvta.to.shared.u64 t, %1; cvt.u32.u64 %0, t; }" : "=r"(a) : "l"(p));
    return a;
}
__device__ __forceinline__ void ldmx4(uint32_t& r0, uint32_t& r1, uint32_t& r2, uint32_t& r3,
                                      uint32_t addr) {
    asm volatile("ldmatrix.sync.aligned.m8n8.x4.shared.b16 {%0,%1,%2,%3}, [%4];"
                 : "=r"(r0), "=r"(r1), "=r"(r2), "=r"(r3) : "r"(addr));
}
__device__ __forceinline__ void mma16816(float* c,
                                         uint32_t a0, uint32_t a1, uint32_t a2, uint32_t a3,
                                         uint32_t b0, uint32_t b1) {
    asm volatile("mma.sync.aligned.m16n8k16.row.col.f32.bf16.bf16.f32 "
                 "{%0,%1,%2,%3}, {%4,%5,%6,%7}, {%8,%9}, {%0,%1,%2,%3};"
                 : "+f"(c[0]), "+f"(c[1]), "+f"(c[2]), "+f"(c[3])
                 : "r"(a0), "r"(a1), "r"(a2), "r"(a3), "r"(b0), "r"(b1));
}
__device__ __forceinline__ uint32_t bf16x2(float a, float b) {
    __nv_bfloat16 h0 = __float2bfloat16(a), h1 = __float2bfloat16(b);
    return (uint32_t)__bfloat16_as_ushort(h0) | ((uint32_t)__bfloat16_as_ushort(h1) << 16);
}
__device__ __forceinline__ float bf16lo_res(float v) {   // residual after bf16 round
    return v - __bfloat162float(__float2bfloat16(v));
}

// ---------------------------------------------------------------------------
// Prep: split W{q,k,v} into bf16 hi/lo, K-major [192][1024]
// ---------------------------------------------------------------------------
__global__ __launch_bounds__(256) void prep_B_kernel(
    const float* __restrict__ Wq, const float* __restrict__ Wk, const float* __restrict__ Wv)
{
    int idx = blockIdx.x * 256 + threadIdx.x;
    int n = idx >> 10, k = idx & 1023;
    const float* W = (n < 64) ? Wq : (n < 128) ? Wk : Wv;
    float v = W[k * 64 + (n & 63)];
    __nv_bfloat16 h = __float2bfloat16(v);
    g_Bhi[idx] = h;
    g_Blo[idx] = __float2bfloat16(v - __bfloat162float(h));
}

// ---------------------------------------------------------------------------
// Projection GEMM (HMMA bf16 hi/lo split). M=128 x N=192 per CTA, 16 warps.
// Epilogue: RoPE, then write Q/K bf16 hi/lo row-major; V bf16 hi/lo transposed.
// ---------------------------------------------------------------------------
#define PA_STR 72
#define SM_AHI 0
#define SM_ALO (128*PA_STR*2)
#define SM_BHI (2*128*PA_STR*2)
#define SM_BLO (SM_BHI + 192*PA_STR*2)
#define SM_TOT (SM_BLO + 192*PA_STR*2)

__global__ __launch_bounds__(512) void proj_gemm_kernel(const float* __restrict__ x)
{
    extern __shared__ char smem[];
    const uint32_t sbase = smem_u32(smem);
    const int tid    = threadIdx.x;
    const int wid    = tid >> 5;
    const int lane   = tid & 31;
    const int warp_m = wid >> 2;
    const int warp_n = wid & 3;
    const int m0     = blockIdx.x * 128;

    uint32_t aOff[2], bOff[3];
    {
        int mlo = (lane >> 3) & 1, khi = (lane >> 4) & 1, r8 = lane & 7;
        #pragma unroll
        for (int mt = 0; mt < 2; mt++)
            aOff[mt] = (uint32_t)((warp_m*32 + mt*16 + mlo*8 + r8) * (PA_STR*2) + khi*16);
        #pragma unroll
        for (int p = 0; p < 3; p++)
            bOff[p] = (uint32_t)((warp_n*48 + p*16 + khi*8 + r8) * (PA_STR*2) + mlo*16);
    }

    float acc[2][6][4];
    #pragma unroll
    for (int mt = 0; mt < 2; mt++)
        #pragma unroll
        for (int nt = 0; nt < 6; nt++)
            #pragma unroll
            for (int q = 0; q < 4; q++) acc[mt][nt][q] = 0.f;

    #pragma unroll 1
    for (int c = 0; c < 16; c++) {
        const int kc = c * 64;
        if (c > 0) __syncthreads();

        #pragma unroll
        for (int it = tid; it < 2048; it += 512) {
            int r = it >> 4, q = it & 15;
            float4 f = *reinterpret_cast<const float4*>(x + (size_t)(m0 + r) * C_ + kc + q*4);
            uint32_t h0 = bf16x2(f.x, f.y), h1 = bf16x2(f.z, f.w);
            uint32_t l0 = bf16x2(bf16lo_res(f.x), bf16lo_res(f.y));
            uint32_t l1 = bf16x2(bf16lo_res(f.z), bf16lo_res(f.w));
            uint32_t off = (uint32_t)(r * (PA_STR*2) + q * 8);
            *reinterpret_cast<uint2*>(smem + SM_AHI + off) = make_uint2(h0, h1);
            *reinterpret_cast<uint2*>(smem + SM_ALO + off) = make_uint2(l0, l1);
        }
        #pragma unroll
        for (int it = tid; it < 1536; it += 512) {
            int n = it >> 3, s = it & 7;
            uint32_t off = (uint32_t)(n * (PA_STR*2) + s * 16);
            *reinterpret_cast<uint4*>(smem + SM_BHI + off) =
                *reinterpret_cast<const uint4*>(g_Bhi + (size_t)n * 1024 + kc + s*8);
            *reinterpret_cast<uint4*>(smem + SM_BLO + off) =
                *reinterpret_cast<const uint4*>(g_Blo + (size_t)n * 1024 + kc + s*8);
        }
        __syncthreads();

        #pragma unroll 1
        for (int pass = 0; pass < 3; pass++) {
            uint32_t aBase = sbase + ((pass < 2) ? SM_AHI : SM_ALO);
            uint32_t bBase = sbase + ((pass == 1) ? SM_BLO : SM_BHI);
            #pragma unroll
            for (int ks = 0; ks < 4; ks++) {
                uint32_t kb = (uint32_t)(ks * 32);
                uint32_t a[2][4];
                #pragma unroll
                for (int mt = 0; mt < 2; mt++)
                    ldmx4(a[mt][0], a[mt][1], a[mt][2], a[mt][3], aBase + aOff[mt] + kb);
                uint32_t b[6][2];
                #pragma unroll
                for (int p = 0; p < 3; p++) {
                    uint32_t r0, r1, r2, r3;
                    ldmx4(r0, r1, r2, r3, bBase + bOff[p] + kb);
                    b[p*2][0] = r0; b[p*2][1] = r1;
                    b[p*2+1][0] = r2; b[p*2+1][1] = r3;
                }
                #pragma unroll
                for (int mt = 0; mt < 2; mt++)
                    #pragma unroll
                    for (int nt = 0; nt < 6; nt++)
                        mma16816(acc[mt][nt], a[mt][0], a[mt][1], a[mt][2], a[mt][3],
                                 b[nt][0], b[nt][1]);
            }
        }
    }

    // ---- Epilogue: RoPE + bf16 hi/lo stores (V transposed) ----
    const int g  = lane >> 2;
    const int tq = lane & 3;
    #pragma unroll
    for (int mt = 0; mt < 2; mt++) {
        int row0 = m0 + warp_m*32 + mt*16 + g;
        int rows[2] = { row0, row0 + 8 };
        #pragma unroll
        for (int nt = 0; nt < 6; nt++) {
            int col = warp_n*48 + nt*8 + 2*tq;
            int mat = col >> 6;
            int col_in = col & 63;
            if (mat < 2) {
                __nv_bfloat16* dhi = (mat == 0) ? g_Qhi : g_Khi;
                __nv_bfloat16* dlo = (mat == 0) ? g_Qlo : g_Klo;
                int pi = col_in >> 1;
                float inv = powf(10000.f, -(float)pi * (1.f / 32.f));
                #pragma unroll
                for (int rg = 0; rg < 2; rg++) {
                    int t = rows[rg] & (T_ - 1);
                    float sn, cs;
                    sincosf((float)t * inv, &sn, &cs);
                    float a0 = acc[mt][nt][rg*2], a1 = acc[mt][nt][rg*2 + 1];
                    float v0 = a0*cs - a1*sn, v1 = a1*cs + a0*sn;
                    size_t base = (size_t)rows[rg] * H_ + col_in;
                    *reinterpret_cast<uint32_t*>(&dhi[base]) = bf16x2(v0, v1);
                    *reinterpret_cast<uint32_t*>(&dlo[base]) = bf16x2(bf16lo_res(v0), bf16lo_res(v1));
                }
            } else {
                #pragma unroll
                for (int rg = 0; rg < 2; rg++) {
                    int bb = rows[rg] >> 11, tt = rows[rg] & (T_ - 1);
                    #pragma unroll
                    for (int e = 0; e < 2; e++) {
                        float v = acc[mt][nt][rg*2 + e];
                        size_t idx = ((size_t)bb * H_ + (col_in + e)) * T_ + tt;
                        g_VThi[idx] = __float2bfloat16(v);
                        g_VTlo[idx] = __float2bfloat16(bf16lo_res(v));
                    }
                }
            }
        }
    }
}

// ---------------------------------------------------------------------------
// Attention on mma.sync: 64-query tile, 4 warps (16 rows each), KV tiles of 64.
// S = Qhi*Khi + Qhi*Klo + Qlo*Khi; P split hi/lo in registers (C-frag == A-frag);
// O += Phi*Vhi + Phi*Vlo + Plo*Vhi with V^T as B operand.
// CTA pairs (qt, 31-qt): 33 iters each, 128 uniform CTAs.
// ---------------------------------------------------------------------------
#define ASTR 72
#define AQHI 0
#define AQLO (64*ASTR*2)
#define AKHI (2*64*ASTR*2)
#define AKLO (3*64*ASTR*2)
#define AVHI (4*64*ASTR*2)
#define AVLO (5*64*ASTR*2)
#define ASM_TOT (6*64*ASTR*2)

__global__ __launch_bounds__(128) void attn_mma_kernel(float* __restrict__ out)
{
    extern __shared__ char smem[];
    const uint32_t sbase = smem_u32(smem);
    const int tid  = threadIdx.x;
    const int wid  = tid >> 5;
    const int lane = tid & 31;
    const int b    = blockIdx.y;
    const int r8   = lane & 7;
    const int mlo  = (lane >> 3) & 1;
    const int khi  = (lane >> 4) & 1;
    const int g    = lane >> 2;
    const int tq   = lane & 3;
    const float scale = 0.125f;

    const uint32_t aRowOff = (uint32_t)((wid*16 + mlo*8 + r8) * (ASTR*2) + khi*16);
    uint32_t bRowOff[4];
    #pragma unroll
    for (int p = 0; p < 4; p++)
        bRowOff[p] = (uint32_t)((p*16 + khi*8 + r8) * (ASTR*2) + mlo*16);

    #pragma unroll 1
    for (int pass = 0; pass < 2; pass++) {
        const int qt = pass ? (31 - (int)blockIdx.x) : (int)blockIdx.x;

        // ---- stage Q tile (bf16 hi/lo) ----
        __syncthreads();
        {
            const __nv_bfloat16* Qh = g_Qhi + ((size_t)b * T_ + qt*64) * H_;
            const __nv_bfloat16* Ql = g_Qlo + ((size_t)b * T_ + qt*64) * H_;
            #pragma unroll
            for (int it = tid; it < 512; it += 128) {
                int r = it >> 3, s = it & 7;
                uint32_t off = (uint32_t)(r * (ASTR*2) + s*16);
                *reinterpret_cast<uint4*>(smem + AQHI + off) =
                    *reinterpret_cast<const uint4*>(Qh + r*64 + s*8);
                *reinterpret_cast<uint4*>(smem + AQLO + off) =
                    *reinterpret_cast<const uint4*>(Ql + r*64 + s*8);
            }
        }
        __syncthreads();

        uint32_t qh[4][4], ql[4][4];
        #pragma unroll
        for (int ks = 0; ks < 4; ks++) {
            ldmx4(qh[ks][0], qh[ks][1], qh[ks][2], qh[ks][3], sbase + AQHI + aRowOff + ks*32);
            ldmx4(ql[ks][0], ql[ks][1], ql[ks][2], ql[ks][3], sbase + AQLO + aRowOff + ks*32);
        }

        float m0r = -1e30f, m1r = -1e30f, l0 = 0.f, l1 = 0.f;
        float o[8][4];
        #pragma unroll
        for (int nt = 0; nt < 8; nt++)
            #pragma unroll
            for (int q = 0; q < 4; q++) o[nt][q] = 0.f;

        #pragma unroll 1
        for (int kt = 0; kt <= qt; kt++) {
            // ---- stage K and V^T tiles ----
            __syncthreads();
            {
                const __nv_bfloat16* Kh = g_Khi + ((size_t)b * T_ + kt*64) * H_;
                const __nv_bfloat16* Kl = g_Klo + ((size_t)b * T_ + kt*64) * H_;
                #pragma unroll
                for (int it = tid; it < 512; it += 128) {
                    int r = it >> 3, s = it & 7;
                    uint32_t off = (uint32_t)(r * (ASTR*2) + s*16);
                    *reinterpret_cast<uint4*>(smem + AKHI + off) =
                        *reinterpret_cast<const uint4*>(Kh + r*64 + s*8);
                    *reinterpret_cast<uint4*>(smem + AKLO + off) =
                        *reinterpret_cast<const uint4*>(Kl + r*64 + s*8);
                    size_t vsrc = ((size_t)b * H_ + r) * T_ + kt*64 + s*8;
                    *reinterpret_cast<uint4*>(smem + AVHI + off) =
                        *reinterpret_cast<const uint4*>(g_VThi + vsrc);
                    *reinterpret_cast<uint4*>(smem + AVLO + off) =
                        *reinterpret_cast<const uint4*>(g_VTlo + vsrc);
                }
            }
            __syncthreads();

            // ---- S = Q K^T (3 split passes, fp32 accum) ----
            float s_[8][4];
            #pragma unroll
            for (int nt = 0; nt < 8; nt++)
                #pragma unroll
                for (int q = 0; q < 4; q++) s_[nt][q] = 0.f;

            #pragma unroll
            for (int ks = 0; ks < 4; ks++) {
                uint32_t kb = (uint32_t)(ks * 32);
                uint32_t kh_[4][4], kl_[4][4];
                #pragma unroll
                for (int p = 0; p < 4; p++) {
                    ldmx4(kh_[p][0], kh_[p][1], kh_[p][2], kh_[p][3], sbase + AKHI + bRowOff[p] + kb);
                    ldmx4(kl_[p][0], kl_[p][1], kl_[p][2], kl_[p][3], sbase + AKLO + bRowOff[p] + kb);
                }
                #pragma unroll
                for (int p = 0; p < 4; p++) {
                    mma16816(s_[2*p],   qh[ks][0], qh[ks][1], qh[ks][2], qh[ks][3], kh_[p][0], kh_[p][1]);
                    mma16816(s_[2*p+1], qh[ks][0], qh[ks][1], qh[ks][2], qh[ks][3], kh_[p][2], kh_[p][3]);
                    mma16816(s_[2*p],   qh[ks][0], qh[ks][1], qh[ks][2], qh[ks][3], kl_[p][0], kl_[p][1]);
                    mma16816(s_[2*p+1], qh[ks][0], qh[ks][1], qh[ks][2], qh[ks][3], kl_[p][2], kl_[p][3]);
                    mma16816(s_[2*p],   ql[ks][0], ql[ks][1], ql[ks][2], ql[ks][3], kh_[p][0], kh_[p][1]);
                    mma16816(s_[2*p+1], ql[ks][0], ql[ks][1], ql[ks][2], ql[ks][3], kh_[p][2], kh_[p][3]);
                }
            }

            // ---- scale + causal mask ----
            #pragma unroll
            for (int nt = 0; nt < 8; nt++)
                #pragma unroll
                for (int q = 0; q < 4; q++) s_[nt][q] *= scale;
            if (kt == qt) {
                int qr0 = qt*64 + wid*16 + g;
                #pragma unroll
                for (int nt = 0; nt < 8; nt++) {
                    int kc0 = kt*64 + nt*8 + 2*tq;
                    if (kc0     > qr0)     s_[nt][0] = -1e30f;
                    if (kc0 + 1 > qr0)     s_[nt][1] = -1e30f;
                    if (kc0     > qr0 + 8) s_[nt][2] = -1e30f;
                    if (kc0 + 1 > qr0 + 8) s_[nt][3] = -1e30f;
                }
            }

            // ---- online softmax (rows g, g+8; quad = lanes xor 1,2) ----
            float mx0 = -1e30f, mx1 = -1e30f;
            #pragma unroll
            for (int nt = 0; nt < 8; nt++) {
                mx0 = fmaxf(mx0, fmaxf(s_[nt][0], s_[nt][1]));
                mx1 = fmaxf(mx1, fmaxf(s_[nt][2], s_[nt][3]));
            }
            mx0 = fmaxf(mx0, __shfl_xor_sync(0xffffffffu, mx0, 1));
            mx0 = fmaxf(mx0, __shfl_xor_sync(0xffffffffu, mx0, 2));
            mx1 = fmaxf(mx1, __shfl_xor_sync(0xffffffffu, mx1, 1));
            mx1 = fmaxf(mx1, __shfl_xor_sync(0xffffffffu, mx1, 2));
            float mn0 = fmaxf(m0r, mx0), mn1 = fmaxf(m1r, mx1);
            float al0 = __expf(m0r - mn0), al1 = __expf(m1r - mn1);
            float rs0 = 0.f, rs1 = 0.f;
            #pragma unroll
            for (int nt = 0; nt < 8; nt++) {
                s_[nt][0] = __expf(s_[nt][0] - mn0);
                s_[nt][1] = __expf(s_[nt][1] - mn0);
                s_[nt][2] = __expf(s_[nt][2] - mn1);
                s_[nt][3] = __expf(s_[nt][3] - mn1);
                rs0 += s_[nt][0] + s_[nt][1];
                rs1 += s_[nt][2] + s_[nt][3];
            }
            rs0 += __shfl_xor_sync(0xffffffffu, rs0, 1);
            rs0 += __shfl_xor_sync(0xffffffffu, rs0, 2);
            rs1 += __shfl_xor_sync(0xffffffffu, rs1, 1);
            rs1 += __shfl_xor_sync(0xffffffffu, rs1, 2);
            l0 = l0 * al0 + rs0;  l1 = l1 * al1 + rs1;
            m0r = mn0;  m1r = mn1;
            #pragma unroll
            for (int nt = 0; nt < 8; nt++) {
                o[nt][0] *= al0; o[nt][1] *= al0;
                o[nt][2] *= al1; o[nt][3] *= al1;
            }

            // ---- O += P V (P hi/lo from S fragments; V^T from smem) ----
            #pragma unroll
            for (int kk = 0; kk < 4; kk++) {
                uint32_t ah[4], al_[4];
                ah[0] = bf16x2(s_[2*kk][0],   s_[2*kk][1]);
                ah[1] = bf16x2(s_[2*kk][2],   s_[2*kk][3]);
                ah[2] = bf16x2(s_[2*kk+1][0], s_[2*kk+1][1]);
                ah[3] = bf16x2(s_[2*kk+1][2], s_[2*kk+1][3]);
                al_[0] = bf16x2(bf16lo_res(s_[2*kk][0]),   bf16lo_res(s_[2*kk][1]));
                al_[1] = bf16x2(bf16lo_res(s_[2*kk][2]),   bf16lo_res(s_[2*kk][3]));
                al_[2] = bf16x2(bf16lo_res(s_[2*kk+1][0]), bf16lo_res(s_[2*kk+1][1]));
                al_[3] = bf16x2(bf16lo_res(s_[2*kk+1][2]), bf16lo_res(s_[2*kk+1][3]));
                uint32_t kb = (uint32_t)(kk * 32);
                #pragma unroll
                for (int p = 0; p < 4; p++) {
                    uint32_t vh0, vh1, vh2, vh3, vl0, vl1, vl2, vl3;
                    ldmx4(vh0, vh1, vh2, vh3, sbase + AVHI + bRowOff[p] + kb);
                    ldmx4(vl0, vl1, vl2, vl3, sbase + AVLO + bRowOff[p] + kb);
                    mma16816(o[2*p],   ah[0], ah[1], ah[2], ah[3], vh0, vh1);
                    mma16816(o[2*p+1], ah[0], ah[1], ah[2], ah[3], vh2, vh3);
                    mma16816(o[2*p],   ah[0], ah[1], ah[2], ah[3], vl0, vl1);
                    mma16816(o[2*p+1], ah[0], ah[1], ah[2], ah[3], vl2, vl3);
                    mma16816(o[2*p],   al_[0], al_[1], al_[2], al_[3], vh0, vh1);
                    mma16816(o[2*p+1], al_[0], al_[1], al_[2], al_[3], vh2, vh3);
                }
            }
        }

        // ---- epilogue ----
        float rc0 = 1.f / l0, rc1 = 1.f / l1;
        int qr0 = qt*64 + wid*16 + g;
        #pragma unroll
        for (int nt = 0; nt < 8; nt++) {
            int col = nt*8 + 2*tq;
            *reinterpret_cast<float2*>(&out[((size_t)b*T_ + qr0) * H_ + col]) =
                make_float2(o[nt][0]*rc0, o[nt][1]*rc0);
            *reinterpret_cast<float2*>(&out[((size_t)b*T_ + qr0 + 8) * H_ + col]) =
                make_float2(o[nt][2]*rc1, o[nt][3]*rc1);
        }
    }
}

extern "C" void kernel_launch(void* const* d_in, const int* in_sizes, int n_in,
                              void* d_out, int out_size)
{
    const float* x  = (const float*)d_in[0];
    const float* Wq = (const float*)d_in[1];
    const float* Wk = (const float*)d_in[2];
    const float* Wv = (const float*)d_in[3];
    float* out = (float*)d_out;

    cudaFuncSetAttribute(proj_gemm_kernel,
                         cudaFuncAttributeMaxDynamicSharedMemorySize, SM_TOT);
    cudaFuncSetAttribute(attn_mma_kernel,
                         cudaFuncAttributeMaxDynamicSharedMemorySize, ASM_TOT);

    prep_B_kernel<<<(192 * 1024) / 256, 256>>>(Wq, Wk, Wv);
    proj_gemm_kernel<<<(B_ * T_) / 128, 512, SM_TOT>>>(x);
    attn_mma_kernel<<<dim3(16, B_), 128, ASM_TOT>>>(out);
}

// round 6
// speedup vs baseline: 3.6678x; 1.0358x over previous
#include <cuda_runtime.h>
#include <cuda_bf16.h>
#include <math.h>
#include <stdint.h>

#define B_ 8
#define T_ 2048
#define C_ 1024
#define H_ 64

// Q/K post-RoPE, bf16 hi/lo, row-major [B*T][64]
__device__ __align__(16) __nv_bfloat16 g_Qhi[B_*T_*H_];
__device__ __align__(16) __nv_bfloat16 g_Qlo[B_*T_*H_];
__device__ __align__(16) __nv_bfloat16 g_Khi[B_*T_*H_];
__device__ __align__(16) __nv_bfloat16 g_Klo[B_*T_*H_];
// V transposed [B][64 h][T], bf16 hi/lo
__device__ __align__(16) __nv_bfloat16 g_VThi[B_*H_*T_];
__device__ __align__(16) __nv_bfloat16 g_VTlo[B_*H_*T_];
// W split bf16 hi/lo, K-major [192][1024]
__device__ __align__(16) __nv_bfloat16 g_Bhi[192*1024];
__device__ __align__(16) __nv_bfloat16 g_Blo[192*1024];

__device__ __forceinline__ uint32_t smem_u32(const void* p) {
    uint32_t a;
    asm("{ .reg .u64 t; cvta.to.shared.u64 t, %1; cvt.u32.u64 %0, t; }" : "=r"(a) : "l"(p));
    return a;
}
__device__ __forceinline__ void ldmx4(uint32_t& r0, uint32_t& r1, uint32_t& r2, uint32_t& r3,
                                      uint32_t addr) {
    asm volatile("ldmatrix.sync.aligned.m8n8.x4.shared.b16 {%0,%1,%2,%3}, [%4];"
                 : "=r"(r0), "=r"(r1), "=r"(r2), "=r"(r3) : "r"(addr));
}
__device__ __forceinline__ void mma16816(float* c,
                                         uint32_t a0, uint32_t a1, uint32_t a2, uint32_t a3,
                                         uint32_t b0, uint32_t b1) {
    asm volatile("mma.sync.aligned.m16n8k16.row.col.f32.bf16.bf16.f32 "
                 "{%0,%1,%2,%3}, {%4,%5,%6,%7}, {%8,%9}, {%0,%1,%2,%3};"
                 : "+f"(c[0]), "+f"(c[1]), "+f"(c[2]), "+f"(c[3])
                 : "r"(a0), "r"(a1), "r"(a2), "r"(a3), "r"(b0), "r"(b1));
}
__device__ __forceinline__ uint32_t bf16x2(float a, float b) {
    __nv_bfloat16 h0 = __float2bfloat16(a), h1 = __float2bfloat16(b);
    return (uint32_t)__bfloat16_as_ushort(h0) | ((uint32_t)__bfloat16_as_ushort(h1) << 16);
}
__device__ __forceinline__ float bf16lo_res(float v) {
    return v - __bfloat162float(__float2bfloat16(v));
}
#define CP_A16(dst, src) \
    asm volatile("cp.async.cg.shared.global [%0], [%1], 16;" :: "r"(dst), "l"(src))
#define CP_COMMIT() asm volatile("cp.async.commit_group;" ::: "memory")
#define CP_WAIT0()  asm volatile("cp.async.wait_group 0;" ::: "memory")
#define CP_WAIT1()  asm volatile("cp.async.wait_group 1;" ::: "memory")

// ---------------------------------------------------------------------------
// Prep: split W{q,k,v} into bf16 hi/lo, K-major [192][1024]
// ---------------------------------------------------------------------------
__global__ __launch_bounds__(256) void prep_B_kernel(
    const float* __restrict__ Wq, const float* __restrict__ Wk, const float* __restrict__ Wv)
{
    int idx = blockIdx.x * 256 + threadIdx.x;
    int n = idx >> 10, k = idx & 1023;
    const float* W = (n < 64) ? Wq : (n < 128) ? Wk : Wv;
    float v = W[k * 64 + (n & 63)];
    __nv_bfloat16 h = __float2bfloat16(v);
    g_Bhi[idx] = h;
    g_Blo[idx] = __float2bfloat16(v - __bfloat162float(h));
}

// ---------------------------------------------------------------------------
// Projection GEMM (HMMA bf16 hi/lo split). M=128 x N=192 per CTA, 16 warps.
// Epilogue: RoPE, write Q/K bf16 hi/lo row-major; V bf16 hi/lo transposed.
// ---------------------------------------------------------------------------
#define PA_STR 72
#define SM_AHI 0
#define SM_ALO (128*PA_STR*2)
#define SM_BHI (2*128*PA_STR*2)
#define SM_BLO (SM_BHI + 192*PA_STR*2)
#define SM_TOT (SM_BLO + 192*PA_STR*2)

__global__ __launch_bounds__(512) void proj_gemm_kernel(const float* __restrict__ x)
{
    extern __shared__ char smem[];
    const uint32_t sbase = smem_u32(smem);
    const int tid    = threadIdx.x;
    const int wid    = tid >> 5;
    const int lane   = tid & 31;
    const int warp_m = wid >> 2;
    const int warp_n = wid & 3;
    const int m0     = blockIdx.x * 128;

    uint32_t aOff[2], bOff[3];
    {
        int mlo = (lane >> 3) & 1, khi = (lane >> 4) & 1, r8 = lane & 7;
        #pragma unroll
        for (int mt = 0; mt < 2; mt++)
            aOff[mt] = (uint32_t)((warp_m*32 + mt*16 + mlo*8 + r8) * (PA_STR*2) + khi*16);
        #pragma unroll
        for (int p = 0; p < 3; p++)
            bOff[p] = (uint32_t)((warp_n*48 + p*16 + khi*8 + r8) * (PA_STR*2) + mlo*16);
    }

    float acc[2][6][4];
    #pragma unroll
    for (int mt = 0; mt < 2; mt++)
        #pragma unroll
        for (int nt = 0; nt < 6; nt++)
            #pragma unroll
            for (int q = 0; q < 4; q++) acc[mt][nt][q] = 0.f;

    #pragma unroll 1
    for (int c = 0; c < 16; c++) {
        const int kc = c * 64;
        if (c > 0) __syncthreads();

        #pragma unroll
        for (int it = tid; it < 2048; it += 512) {
            int r = it >> 4, q = it & 15;
            float4 f = *reinterpret_cast<const float4*>(x + (size_t)(m0 + r) * C_ + kc + q*4);
            uint32_t h0 = bf16x2(f.x, f.y), h1 = bf16x2(f.z, f.w);
            uint32_t l0 = bf16x2(bf16lo_res(f.x), bf16lo_res(f.y));
            uint32_t l1 = bf16x2(bf16lo_res(f.z), bf16lo_res(f.w));
            uint32_t off = (uint32_t)(r * (PA_STR*2) + q * 8);
            *reinterpret_cast<uint2*>(smem + SM_AHI + off) = make_uint2(h0, h1);
            *reinterpret_cast<uint2*>(smem + SM_ALO + off) = make_uint2(l0, l1);
        }
        #pragma unroll
        for (int it = tid; it < 1536; it += 512) {
            int n = it >> 3, s = it & 7;
            uint32_t off = (uint32_t)(n * (PA_STR*2) + s * 16);
            *reinterpret_cast<uint4*>(smem + SM_BHI + off) =
                *reinterpret_cast<const uint4*>(g_Bhi + (size_t)n * 1024 + kc + s*8);
            *reinterpret_cast<uint4*>(smem + SM_BLO + off) =
                *reinterpret_cast<const uint4*>(g_Blo + (size_t)n * 1024 + kc + s*8);
        }
        __syncthreads();

        #pragma unroll 1
        for (int pass = 0; pass < 3; pass++) {
            uint32_t aBase = sbase + ((pass < 2) ? SM_AHI : SM_ALO);
            uint32_t bBase = sbase + ((pass == 1) ? SM_BLO : SM_BHI);
            #pragma unroll
            for (int ks = 0; ks < 4; ks++) {
                uint32_t kb = (uint32_t)(ks * 32);
                uint32_t a[2][4];
                #pragma unroll
                for (int mt = 0; mt < 2; mt++)
                    ldmx4(a[mt][0], a[mt][1], a[mt][2], a[mt][3], aBase + aOff[mt] + kb);
                uint32_t b[6][2];
                #pragma unroll
                for (int p = 0; p < 3; p++) {
                    uint32_t r0, r1, r2, r3;
                    ldmx4(r0, r1, r2, r3, bBase + bOff[p] + kb);
                    b[p*2][0] = r0; b[p*2][1] = r1;
                    b[p*2+1][0] = r2; b[p*2+1][1] = r3;
                }
                #pragma unroll
                for (int mt = 0; mt < 2; mt++)
                    #pragma unroll
                    for (int nt = 0; nt < 6; nt++)
                        mma16816(acc[mt][nt], a[mt][0], a[mt][1], a[mt][2], a[mt][3],
                                 b[nt][0], b[nt][1]);
            }
        }
    }

    const int g  = lane >> 2;
    const int tq = lane & 3;
    #pragma unroll
    for (int mt = 0; mt < 2; mt++) {
        int row0 = m0 + warp_m*32 + mt*16 + g;
        int rows[2] = { row0, row0 + 8 };
        #pragma unroll
        for (int nt = 0; nt < 6; nt++) {
            int col = warp_n*48 + nt*8 + 2*tq;
            int mat = col >> 6;
            int col_in = col & 63;
            if (mat < 2) {
                __nv_bfloat16* dhi = (mat == 0) ? g_Qhi : g_Khi;
                __nv_bfloat16* dlo = (mat == 0) ? g_Qlo : g_Klo;
                int pi = col_in >> 1;
                float inv = powf(10000.f, -(float)pi * (1.f / 32.f));
                #pragma unroll
                for (int rg = 0; rg < 2; rg++) {
                    int t = rows[rg] & (T_ - 1);
                    float sn, cs;
                    sincosf((float)t * inv, &sn, &cs);
                    float a0 = acc[mt][nt][rg*2], a1 = acc[mt][nt][rg*2 + 1];
                    float v0 = a0*cs - a1*sn, v1 = a1*cs + a0*sn;
                    size_t base = (size_t)rows[rg] * H_ + col_in;
                    *reinterpret_cast<uint32_t*>(&dhi[base]) = bf16x2(v0, v1);
                    *reinterpret_cast<uint32_t*>(&dlo[base]) = bf16x2(bf16lo_res(v0), bf16lo_res(v1));
                }
            } else {
                #pragma unroll
                for (int rg = 0; rg < 2; rg++) {
                    int bb = rows[rg] >> 11, tt = rows[rg] & (T_ - 1);
                    #pragma unroll
                    for (int e = 0; e < 2; e++) {
                        float v = acc[mt][nt][rg*2 + e];
                        size_t idx = ((size_t)bb * H_ + (col_in + e)) * T_ + tt;
                        g_VThi[idx] = __float2bfloat16(v);
                        g_VTlo[idx] = __float2bfloat16(bf16lo_res(v));
                    }
                }
            }
        }
    }
}

// ---------------------------------------------------------------------------
// Attention on mma.sync, cp.async double-buffered K/V staging.
// 64-query tile, 4 warps (16 rows each). S = Qhi*Khi + Qhi*Klo + Qlo*Khi;
// P re-split hi/lo in registers; O += Phi*Vhi + Phi*Vlo + Plo*Vhi (V^T as B).
// CTA pairs (qt, 31-qt): 33 iters each, 128 uniform CTAs.
// smem: Q hi/lo + 2 x (K hi/lo + V^T hi/lo) double buffer.
// ---------------------------------------------------------------------------
#define ASTR   72
#define TILE_B (64*ASTR*2)          // 9216 bytes per 64x64 bf16 tile
#define AQHI   0
#define AQLO   TILE_B
#define AKV0   (2*TILE_B)           // buffer 0: KHI,KLO,VHI,VLO
#define AKV1   (6*TILE_B)           // buffer 1
#define ASM_TOT (10*TILE_B)         // 92160

__device__ __forceinline__ void stage_kv(uint32_t sdst, int b, int kt, int tid) {
    const __nv_bfloat16* Kh = g_Khi + ((size_t)b * T_ + kt*64) * H_;
    const __nv_bfloat16* Kl = g_Klo + ((size_t)b * T_ + kt*64) * H_;
    #pragma unroll
    for (int it = tid; it < 512; it += 128) {
        int r = it >> 3, s = it & 7;
        uint32_t off = (uint32_t)(r * (ASTR*2) + s*16);
        CP_A16(sdst + off,            Kh + r*64 + s*8);
        CP_A16(sdst + TILE_B + off,   Kl + r*64 + s*8);
        size_t vsrc = ((size_t)b * H_ + r) * T_ + kt*64 + s*8;
        CP_A16(sdst + 2*TILE_B + off, g_VThi + vsrc);
        CP_A16(sdst + 3*TILE_B + off, g_VTlo + vsrc);
    }
}

__global__ __launch_bounds__(128) void attn_mma_kernel(float* __restrict__ out)
{
    extern __shared__ char smem[];
    const uint32_t sbase = smem_u32(smem);
    const int tid  = threadIdx.x;
    const int wid  = tid >> 5;
    const int lane = tid & 31;
    const int b    = blockIdx.y;
    const int r8   = lane & 7;
    const int mlo  = (lane >> 3) & 1;
    const int khi  = (lane >> 4) & 1;
    const int g    = lane >> 2;
    const int tq   = lane & 3;
    const float scale = 0.125f;

    const uint32_t aRowOff = (uint32_t)((wid*16 + mlo*8 + r8) * (ASTR*2) + khi*16);
    uint32_t bRowOff[4];
    #pragma unroll
    for (int p = 0; p < 4; p++)
        bRowOff[p] = (uint32_t)((p*16 + khi*8 + r8) * (ASTR*2) + mlo*16);

    #pragma unroll 1
    for (int pass = 0; pass < 2; pass++) {
        const int qt = pass ? (31 - (int)blockIdx.x) : (int)blockIdx.x;

        __syncthreads();   // all buffers free from previous pass

        // ---- stage Q (cp.async) + prefetch kt=0 KV, one group ----
        {
            const __nv_bfloat16* Qh = g_Qhi + ((size_t)b * T_ + qt*64) * H_;
            const __nv_bfloat16* Ql = g_Qlo + ((size_t)b * T_ + qt*64) * H_;
            #pragma unroll
            for (int it = tid; it < 512; it += 128) {
                int r = it >> 3, s = it & 7;
                uint32_t off = (uint32_t)(r * (ASTR*2) + s*16);
                CP_A16(sbase + AQHI + off, Qh + r*64 + s*8);
                CP_A16(sbase + AQLO + off, Ql + r*64 + s*8);
            }
            stage_kv(sbase + AKV0, b, qt*0 /*kt=0*/, tid);
            CP_COMMIT();
        }
        CP_WAIT0();
        __syncthreads();

        uint32_t qh[4][4], ql[4][4];
        #pragma unroll
        for (int ks = 0; ks < 4; ks++) {
            ldmx4(qh[ks][0], qh[ks][1], qh[ks][2], qh[ks][3], sbase + AQHI + aRowOff + ks*32);
            ldmx4(ql[ks][0], ql[ks][1], ql[ks][2], ql[ks][3], sbase + AQLO + aRowOff + ks*32);
        }

        float m0r = -1e30f, m1r = -1e30f, l0 = 0.f, l1 = 0.f;
        float o[8][4];
        #pragma unroll
        for (int nt = 0; nt < 8; nt++)
            #pragma unroll
            for (int q = 0; q < 4; q++) o[nt][q] = 0.f;

        #pragma unroll 1
        for (int kt = 0; kt <= qt; kt++) {
            const uint32_t kvb = sbase + ((kt & 1) ? AKV1 : AKV0);

            // prefetch next tile into the other buffer (its readers finished
            // at the end-of-compute barrier of iteration kt-1)
            if (kt < qt) {
                stage_kv(sbase + (((kt + 1) & 1) ? AKV1 : AKV0), b, kt + 1, tid);
                CP_COMMIT();
                CP_WAIT1();
            } else {
                CP_WAIT0();
            }
            __syncthreads();   // kt's tile visible to all warps

            // ---- S = Q K^T (3 split passes, fp32 accum) ----
            float s_[8][4];
            #pragma unroll
            for (int nt = 0; nt < 8; nt++)
                #pragma unroll
                for (int q = 0; q < 4; q++) s_[nt][q] = 0.f;

            #pragma unroll
            for (int ks = 0; ks < 4; ks++) {
                uint32_t kb = (uint32_t)(ks * 32);
                uint32_t kh_[4][4], kl_[4][4];
                #pragma unroll
                for (int p = 0; p < 4; p++) {
                    ldmx4(kh_[p][0], kh_[p][1], kh_[p][2], kh_[p][3], kvb + bRowOff[p] + kb);
                    ldmx4(kl_[p][0], kl_[p][1], kl_[p][2], kl_[p][3], kvb + TILE_B + bRowOff[p] + kb);
                }
                #pragma unroll
                for (int p = 0; p < 4; p++) {
                    mma16816(s_[2*p],   qh[ks][0], qh[ks][1], qh[ks][2], qh[ks][3], kh_[p][0], kh_[p][1]);
                    mma16816(s_[2*p+1], qh[ks][0], qh[ks][1], qh[ks][2], qh[ks][3], kh_[p][2], kh_[p][3]);
                    mma16816(s_[2*p],   qh[ks][0], qh[ks][1], qh[ks][2], qh[ks][3], kl_[p][0], kl_[p][1]);
                    mma16816(s_[2*p+1], qh[ks][0], qh[ks][1], qh[ks][2], qh[ks][3], kl_[p][2], kl_[p][3]);
                    mma16816(s_[2*p],   ql[ks][0], ql[ks][1], ql[ks][2], ql[ks][3], kh_[p][0], kh_[p][1]);
                    mma16816(s_[2*p+1], ql[ks][0], ql[ks][1], ql[ks][2], ql[ks][3], kh_[p][2], kh_[p][3]);
                }
            }

            #pragma unroll
            for (int nt = 0; nt < 8; nt++)
                #pragma unroll
                for (int q = 0; q < 4; q++) s_[nt][q] *= scale;
            if (kt == qt) {
                int qr0 = qt*64 + wid*16 + g;
                #pragma unroll
                for (int nt = 0; nt < 8; nt++) {
                    int kc0 = kt*64 + nt*8 + 2*tq;
                    if (kc0     > qr0)     s_[nt][0] = -1e30f;
                    if (kc0 + 1 > qr0)     s_[nt][1] = -1e30f;
                    if (kc0     > qr0 + 8) s_[nt][2] = -1e30f;
                    if (kc0 + 1 > qr0 + 8) s_[nt][3] = -1e30f;
                }
            }

            // ---- online softmax ----
            float mx0 = -1e30f, mx1 = -1e30f;
            #pragma unroll
            for (int nt = 0; nt < 8; nt++) {
                mx0 = fmaxf(mx0, fmaxf(s_[nt][0], s_[nt][1]));
                mx1 = fmaxf(mx1, fmaxf(s_[nt][2], s_[nt][3]));
            }
            mx0 = fmaxf(mx0, __shfl_xor_sync(0xffffffffu, mx0, 1));
            mx0 = fmaxf(mx0, __shfl_xor_sync(0xffffffffu, mx0, 2));
            mx1 = fmaxf(mx1, __shfl_xor_sync(0xffffffffu, mx1, 1));
            mx1 = fmaxf(mx1, __shfl_xor_sync(0xffffffffu, mx1, 2));
            float mn0 = fmaxf(m0r, mx0), mn1 = fmaxf(m1r, mx1);
            float al0 = __expf(m0r - mn0), al1 = __expf(m1r - mn1);
            float rs0 = 0.f, rs1 = 0.f;
            #pragma unroll
            for (int nt = 0; nt < 8; nt++) {
                s_[nt][0] = __expf(s_[nt][0] - mn0);
                s_[nt][1] = __expf(s_[nt][1] - mn0);
                s_[nt][2] = __expf(s_[nt][2] - mn1);
                s_[nt][3] = __expf(s_[nt][3] - mn1);
                rs0 += s_[nt][0] + s_[nt][1];
                rs1 += s_[nt][2] + s_[nt][3];
            }
            rs0 += __shfl_xor_sync(0xffffffffu, rs0, 1);
            rs0 += __shfl_xor_sync(0xffffffffu, rs0, 2);
            rs1 += __shfl_xor_sync(0xffffffffu, rs1, 1);
            rs1 += __shfl_xor_sync(0xffffffffu, rs1, 2);
            l0 = l0 * al0 + rs0;  l1 = l1 * al1 + rs1;
            m0r = mn0;  m1r = mn1;
            #pragma unroll
            for (int nt = 0; nt < 8; nt++) {
                o[nt][0] *= al0; o[nt][1] *= al0;
                o[nt][2] *= al1; o[nt][3] *= al1;
            }

            // ---- O += P V ----
            #pragma unroll
            for (int kk = 0; kk < 4; kk++) {
                uint32_t ah[4], al_[4];
                ah[0] = bf16x2(s_[2*kk][0],   s_[2*kk][1]);
                ah[1] = bf16x2(s_[2*kk][2],   s_[2*kk][3]);
                ah[2] = bf16x2(s_[2*kk+1][0], s_[2*kk+1][1]);
                ah[3] = bf16x2(s_[2*kk+1][2], s_[2*kk+1][3]);
                al_[0] = bf16x2(bf16lo_res(s_[2*kk][0]),   bf16lo_res(s_[2*kk][1]));
                al_[1] = bf16x2(bf16lo_res(s_[2*kk][2]),   bf16lo_res(s_[2*kk][3]));
                al_[2] = bf16x2(bf16lo_res(s_[2*kk+1][0]), bf16lo_res(s_[2*kk+1][1]));
                al_[3] = bf16x2(bf16lo_res(s_[2*kk+1][2]), bf16lo_res(s_[2*kk+1][3]));
                uint32_t kb = (uint32_t)(kk * 32);
                #pragma unroll
                for (int p = 0; p < 4; p++) {
                    uint32_t vh0, vh1, vh2, vh3, vl0, vl1, vl2, vl3;
                    ldmx4(vh0, vh1, vh2, vh3, kvb + 2*TILE_B + bRowOff[p] + kb);
                    ldmx4(vl0, vl1, vl2, vl3, kvb + 3*TILE_B + bRowOff[p] + kb);
                    mma16816(o[2*p],   ah[0], ah[1], ah[2], ah[3], vh0, vh1);
                    mma16816(o[2*p+1], ah[0], ah[1], ah[2], ah[3], vh2, vh3);
                    mma16816(o[2*p],   ah[0], ah[1], ah[2], ah[3], vl0, vl1);
                    mma16816(o[2*p+1], ah[0], ah[1], ah[2], ah[3], vl2, vl3);
                    mma16816(o[2*p],   al_[0], al_[1], al_[2], al_[3], vh0, vh1);
                    mma16816(o[2*p+1], al_[0], al_[1], al_[2], al_[3], vh2, vh3);
                }
            }
            __syncthreads();   // all warps done reading kt's buffer
        }

        float rc0 = 1.f / l0, rc1 = 1.f / l1;
        int qr0 = qt*64 + wid*16 + g;
        #pragma unroll
        for (int nt = 0; nt < 8; nt++) {
            int col = nt*8 + 2*tq;
            *reinterpret_cast<float2*>(&out[((size_t)b*T_ + qr0) * H_ + col]) =
                make_float2(o[nt][0]*rc0, o[nt][1]*rc0);
            *reinterpret_cast<float2*>(&out[((size_t)b*T_ + qr0 + 8) * H_ + col]) =
                make_float2(o[nt][2]*rc1, o[nt][3]*rc1);
        }
    }
}

extern "C" void kernel_launch(void* const* d_in, const int* in_sizes, int n_in,
                              void* d_out, int out_size)
{
    const float* x  = (const float*)d_in[0];
    const float* Wq = (const float*)d_in[1];
    const float* Wk = (const float*)d_in[2];
    const float* Wv = (const float*)d_in[3];
    float* out = (float*)d_out;

    cudaFuncSetAttribute(proj_gemm_kernel,
                         cudaFuncAttributeMaxDynamicSharedMemorySize, SM_TOT);
    cudaFuncSetAttribute(attn_mma_kernel,
                         cudaFuncAttributeMaxDynamicSharedMemorySize, ASM_TOT);

    prep_B_kernel<<<(192 * 1024) / 256, 256>>>(Wq, Wk, Wv);
    proj_gemm_kernel<<<(B_ * T_) / 128, 512, SM_TOT>>>(x);
    attn_mma_kernel<<<dim3(16, B_), 128, ASM_TOT>>>(out);
}